// round 11
// baseline (speedup 1.0000x reference)
#include <cuda_runtime.h>
#include <cstdint>
#include <cstddef>

#define N_NODES 40000
#define N_EDGES 640000
#define N_GRAPHS 64
#define NHH 16
#define NT 16384
#define TMIN_T (-8.0f)
#define DT_T (16.0f/(float)(NT-1))
#define INVDT_T ((float)(NT-1)/16.0f)

// ---------------- scratch (device globals; no allocations) ----------------
__device__ __align__(256) float  g_TA [(size_t)NT*256];   // edge matrix table [NT][16][16]
__device__ __align__(256) float  g_TB [(size_t)NT*16];    // edge bias table   [NT][16]
__device__ __align__(256) float  g_h [N_NODES*NHH];
__device__ __align__(256) float  g_m [N_NODES*NHH];
__device__ __align__(256) float  g_nb[N_GRAPHS*256];
__device__ __align__(256) int    g_bin_cnt[NT];           // zero at load; re-zeroed by scan each run
__device__ __align__(256) int    g_bin_cur[NT];           // scatter cursor (reset by scan)
__device__ __align__(256) int    g_bin_start[NT+1];       // bin start offsets + sentinel
__device__ __align__(256) float2 g_bw[N_EDGES];           // cached (w, i0-as-float-bits)
__device__ __align__(256) float4 g_epk[N_EDGES];          // sorted packed edges

__device__ __forceinline__ float selu_f(float x){
    return x > 0.f ? 1.0507009873554805f * x
                   : 1.7580993408473766f * (expf(x) - 1.f);
}
__device__ __forceinline__ float sigmoid_f(float x){
    return 1.f / (1.f + expf(-x));
}
__device__ __forceinline__ void edge_bin(float t, int& i0, float& w){
    float u = (t - TMIN_T) * INVDT_T;
    u = fminf(fmaxf(u, 0.f), (float)(NT - 1));
    int i = (int)u;
    if (i > NT - 2) i = NT - 2;
    i0 = i;
    w  = u - (float)i;
}

// ---------------- launch 0: state init + edge binning + histogram ----------------
__global__ void k_hist_init(const float* __restrict__ x, const float* __restrict__ e){
    int i = blockIdx.x * blockDim.x + threadIdx.x;   // 0..640000
    if (i < N_GRAPHS*256) g_nb[i] = 0.f;
    if (i < N_NODES*NHH){
        g_m[i] = 0.f;
        int n = i >> 4, j = i & 15;
        g_h[i] = (j < 2) ? x[n*2 + j] : 0.f;
    }
    if (i < N_EDGES){
        int i0; float w;
        edge_bin(e[i], i0, w);
        float2 bw; bw.x = w; bw.y = __int_as_float(i0);
        g_bw[i] = bw;
        atomicAdd(&g_bin_cnt[i0], 1);
    }
}

// ---------------- launch 1: table build (blocks 0..1023) + scan (block 1024) ----------------
__global__ void k_scan_table(const float* __restrict__ lw1, const float* __restrict__ lb1,
                             const float* __restrict__ lw2, const float* __restrict__ lb2,
                             const float* __restrict__ bw1, const float* __restrict__ bb1,
                             const float* __restrict__ bw2, const float* __restrict__ bb2){
    const int TP = 16;
    int tid = threadIdx.x;           // 256

    if (blockIdx.x == NT/TP){
        // ---- exclusive scan over NT bins; write start offsets + cursor; re-zero cnt ----
        __shared__ int part[256];
        __shared__ int pref[257];
        int base = tid * (NT/256);
        int s = 0;
        #pragma unroll 4
        for (int i = 0; i < NT/256; i++) s += g_bin_cnt[base + i];
        part[tid] = s;
        __syncthreads();
        if (tid == 0){
            int acc = 0;
            pref[0] = 0;
            for (int i = 0; i < 256; i++){ acc += part[i]; pref[i+1] = acc; }
        }
        __syncthreads();
        int off = pref[tid];
        #pragma unroll 4
        for (int i = 0; i < NT/256; i++){
            int c = g_bin_cnt[base + i];
            g_bin_start[base + i] = off;
            g_bin_cur  [base + i] = off;
            g_bin_cnt  [base + i] = 0;          // restore invariant for next replay
            off += c;
        }
        if (tid == 255) g_bin_start[NT] = N_EDGES;   // sentinel
        return;
    }

    // ---- table build ----
    __shared__ float s_sh [256][TP];
    __shared__ float sb_sh[256][TP];
    int p0 = blockIdx.x * TP;

    float w1  = lw1[tid], b1  = lb1[tid];
    float w1b = bw1[tid], b1b = bb1[tid];
    #pragma unroll
    for (int p = 0; p < TP; p++){
        float t = TMIN_T + (float)(p0 + p) * DT_T;
        s_sh [tid][p] = selu_f(fmaf(t, w1,  b1));
        sb_sh[tid][p] = selu_f(fmaf(t, w1b, b1b));
    }
    __syncthreads();

    float acc[TP];
    float bias = lb2[tid];
    #pragma unroll
    for (int p = 0; p < TP; p++) acc[p] = bias;
    for (int k = 0; k < 256; k++){
        float w = lw2[k*256 + tid];
        const float4* s4 = (const float4*)&s_sh[k][0];
        #pragma unroll
        for (int q = 0; q < TP/4; q++){
            float4 s = s4[q];
            acc[q*4+0] = fmaf(s.x, w, acc[q*4+0]);
            acc[q*4+1] = fmaf(s.y, w, acc[q*4+1]);
            acc[q*4+2] = fmaf(s.z, w, acc[q*4+2]);
            acc[q*4+3] = fmaf(s.w, w, acc[q*4+3]);
        }
    }
    #pragma unroll
    for (int p = 0; p < TP; p++)
        g_TA[(size_t)(p0 + p)*256 + tid] = acc[p];

    int o = tid & 15, p = tid >> 4;
    float acc2 = bb2[o];
    for (int k = 0; k < 256; k++)
        acc2 = fmaf(sb_sh[k][p], bw2[k*16 + o], acc2);
    g_TB[(size_t)(p0 + p)*16 + o] = acc2;
}

// ---------------- launch 2: scatter edges into bin-sorted packed array ----------------
__global__ void k_scatter_e(const int* __restrict__ first, const int* __restrict__ second){
    int idx = blockIdx.x * blockDim.x + threadIdx.x;
    if (idx >= N_EDGES) return;
    float2 bw = g_bw[idx];
    int i0 = __float_as_int(bw.y);
    int pos = atomicAdd(&g_bin_cur[i0], 1);
    float4 pk;
    pk.x = bw.x;
    pk.y = bw.y;
    pk.z = __int_as_float(first[idx]);
    pk.w = __int_as_float(second[idx]);
    g_epk[pos] = pk;
}

// ---------------- message pass: one warp per bin, A rows register-resident ----------------
// lane = (row = l&15, khalf = l>>4). Lane holds half-rows A0[row][khalf*8..] and
// A1[row][khalf*8..] in registers for the whole bin. Per edge: uniform epk load,
// 32B h-half load, 16 FMA, 2 shfl to combine k-halves, 1 contiguous scalar red.
__global__ void __launch_bounds__(256)
k_msg(){
    int gw   = (blockIdx.x * blockDim.x + threadIdx.x) >> 5;   // global warp id = bin
    int lane = threadIdx.x & 31;
    if (gw >= NT) return;
    int row = lane & 15, khalf = lane >> 4;

    int start = g_bin_start[gw];
    int end   = g_bin_start[gw + 1];
    if (start >= end) return;

    const float4* a0p = (const float4*)(g_TA + (size_t)gw*256       + row*16 + khalf*8);
    const float4* a1p = (const float4*)(g_TA + (size_t)(gw+1)*256   + row*16 + khalf*8);
    float4 a00 = a0p[0], a01 = a0p[1];
    float4 a10 = a1p[0], a11 = a1p[1];
    float bias = g_TB[(size_t)(gw + khalf)*16 + row];  // khalf0: b0[row], khalf1: b1[row]
    float pb0 = khalf ? 0.f : bias;
    float pb1 = khalf ? bias : 0.f;

    for (int e = start; e < end; e++){
        float4 pk = g_epk[e];                          // warp-uniform
        float w = pk.x;
        int f = __float_as_int(pk.z);
        int s = __float_as_int(pk.w);
        const float4* hp = (const float4*)(g_h + f * NHH + khalf * 8);
        float4 h0 = hp[0], h1 = hp[1];

        float p0 = pb0, p1 = pb1;
        p0 = fmaf(a00.x, h0.x, p0); p0 = fmaf(a00.y, h0.y, p0);
        p0 = fmaf(a00.z, h0.z, p0); p0 = fmaf(a00.w, h0.w, p0);
        p0 = fmaf(a01.x, h1.x, p0); p0 = fmaf(a01.y, h1.y, p0);
        p0 = fmaf(a01.z, h1.z, p0); p0 = fmaf(a01.w, h1.w, p0);
        p1 = fmaf(a10.x, h0.x, p1); p1 = fmaf(a10.y, h0.y, p1);
        p1 = fmaf(a10.z, h0.z, p1); p1 = fmaf(a10.w, h0.w, p1);
        p1 = fmaf(a11.x, h1.x, p1); p1 = fmaf(a11.y, h1.y, p1);
        p1 = fmaf(a11.z, h1.z, p1); p1 = fmaf(a11.w, h1.w, p1);

        float q0 = __shfl_down_sync(0xffffffffu, p0, 16);
        float q1 = __shfl_down_sync(0xffffffffu, p1, 16);
        float m  = fmaf(1.f - w, p0 + q0, w * (p1 + q1));
        if (lane < 16){
            asm volatile("red.global.add.f32 [%0], %1;"
                         :: "l"(g_m + (size_t)s * NHH + row), "f"(m) : "memory");
        }
    }
}

// ---------------- GRU update: 2 threads per node ----------------
__global__ void k_gru(const float* __restrict__ gk, const float* __restrict__ grk,
                      const float* __restrict__ gb){
    __shared__ float K[16*48], RK[16*48], B[96];
    int tid = threadIdx.x;  // 128
    for (int i = tid; i < 768; i += blockDim.x){ K[i] = gk[i]; RK[i] = grk[i]; }
    if (tid < 96) B[tid] = gb[tid];
    __syncthreads();

    int idx = blockIdx.x * blockDim.x + tid;
    if (idx >= 2*N_NODES) return;
    int n = idx >> 1, half = idx & 1;

    float m[16], h[16];
    float4* mp = (float4*)(g_m + n * NHH);
    float4* hp = (float4*)(g_h + n * NHH);
    #pragma unroll
    for (int q = 0; q < 4; q++){
        float4 a = mp[q]; m[q*4+0]=a.x; m[q*4+1]=a.y; m[q*4+2]=a.z; m[q*4+3]=a.w;
        float4 b = hp[q]; h[q*4+0]=b.x; h[q*4+1]=b.y; h[q*4+2]=b.z; h[q*4+3]=b.w;
    }

    float hn[8];
    int base = half * 8;
    #pragma unroll
    for (int ii = 0; ii < 8; ii++){
        int i = base + ii;
        float xz = B[i], xr = B[16+i], xh = B[32+i];
        float rz = B[48+i], rr = B[64+i], rh = B[80+i];
        #pragma unroll
        for (int j = 0; j < 16; j++){
            float mj = m[j], hj = h[j];
            xz = fmaf(mj, K [j*48 + i],      xz);
            xr = fmaf(mj, K [j*48 + 16 + i], xr);
            xh = fmaf(mj, K [j*48 + 32 + i], xh);
            rz = fmaf(hj, RK[j*48 + i],      rz);
            rr = fmaf(hj, RK[j*48 + 16 + i], rr);
            rh = fmaf(hj, RK[j*48 + 32 + i], rh);
        }
        float z  = sigmoid_f(xz + rz);
        float r  = sigmoid_f(xr + rr);
        float hh = tanhf(fmaf(r, rh, xh));
        hn[ii] = z * h[i] + (1.f - z) * hh;
    }
    float4 zero = {0.f, 0.f, 0.f, 0.f};
    #pragma unroll
    for (int q = 0; q < 2; q++){
        float4 o;
        o.x = hn[q*4+0]; o.y = hn[q*4+1]; o.z = hn[q*4+2]; o.w = hn[q*4+3];
        hp[half*2 + q] = o;
        mp[half*2 + q] = zero;
    }
}

// ---------------- fused readout ----------------
__global__ void __launch_bounds__(256)
k_readout(const float* __restrict__ x, const int* __restrict__ seg,
          const float* __restrict__ iw1, const float* __restrict__ ib1,
          const float* __restrict__ iw2, const float* __restrict__ ib2,
          const float* __restrict__ jw1, const float* __restrict__ jb1,
          const float* __restrict__ jw2, const float* __restrict__ jb2){
    const int NPB = 16;
    __shared__ float2 tu[NPB][256];
    __shared__ float  hx[NPB][18];
    __shared__ int    segs[NPB];
    int n0  = blockIdx.x * NPB;
    int tid = threadIdx.x;   // 256

    for (int i = tid; i < NPB*18; i += 256){
        int p = i / 18, d = i % 18;
        int n = n0 + p;
        hx[p][d] = (d < 16) ? g_h[n*16 + d] : x[n*2 + (d - 16)];
    }
    if (tid < NPB) segs[tid] = seg[n0 + tid];
    __syncthreads();

    {
        float ai[NPB], aj[NPB];
        float bi = ib1[tid], bj = jb1[tid];
        #pragma unroll
        for (int p = 0; p < NPB; p++){ ai[p] = bi; aj[p] = bj; }
        #pragma unroll
        for (int d = 0; d < 18; d++){
            float wi = iw1[d*256 + tid], wj = jw1[d*256 + tid];
            #pragma unroll
            for (int p = 0; p < NPB; p++){
                float hv = hx[p][d];
                ai[p] = fmaf(hv, wi, ai[p]);
                aj[p] = fmaf(hv, wj, aj[p]);
            }
        }
        #pragma unroll
        for (int p = 0; p < NPB; p++){
            float2 v; v.x = tanhf(ai[p]); v.y = selu_f(aj[p]);
            tu[p][tid] = v;
        }
    }
    __syncthreads();

    float g1[NPB], g2[NPB];
    {
        float b2i = ib2[tid], b2j = jb2[tid];
        #pragma unroll
        for (int p = 0; p < NPB; p++){ g1[p] = b2i; g2[p] = b2j; }
        for (int k = 0; k < 256; k++){
            float wi = iw2[(size_t)k*256 + tid];
            float wj = jw2[(size_t)k*256 + tid];
            #pragma unroll
            for (int p = 0; p < NPB; p++){
                float2 v = tu[p][k];
                g1[p] = fmaf(v.x, wi, g1[p]);
                g2[p] = fmaf(v.y, wj, g2[p]);
            }
        }
    }

    int cur = segs[0];
    float acc = 0.f;
    #pragma unroll
    for (int p = 0; p < NPB; p++){
        int s = segs[p];
        if (s != cur){
            atomicAdd(&g_nb[cur*256 + tid], acc);
            acc = 0.f; cur = s;
        }
        acc = fmaf(sigmoid_f(g1[p]), g2[p], acc);
    }
    atomicAdd(&g_nb[cur*256 + tid], acc);
}

// ---------------- final MLP ----------------
__global__ void k_final(const float* __restrict__ fw1, const float* __restrict__ fb1,
                        const float* __restrict__ fw2, const float* __restrict__ fb2,
                        float* __restrict__ out){
    __shared__ float nb_sh[256];
    __shared__ float red[256];
    int g = blockIdx.x, o = threadIdx.x;
    nb_sh[o] = g_nb[g*256 + o];
    __syncthreads();
    float acc = fb1[o];
    for (int k = 0; k < 256; k++)
        acc = fmaf(nb_sh[k], fw1[k*256 + o], acc);
    red[o] = selu_f(acc) * fw2[o];
    __syncthreads();
    for (int s = 128; s > 0; s >>= 1){
        if (o < s) red[o] += red[o + s];
        __syncthreads();
    }
    if (o == 0) out[g] = red[0] + fb2[0];
}

// ---------------- launch ----------------
extern "C" void kernel_launch(void* const* d_in, const int* in_sizes, int n_in,
                              void* d_out, int out_size){
    const float* x       = (const float*)d_in[0];
    const float* e       = (const float*)d_in[1];
    const int*   first   = (const int*)  d_in[2];
    const int*   second  = (const int*)  d_in[3];
    const int*   segment = (const int*)  d_in[4];
    const float* l_w1 = (const float*)d_in[5];
    const float* l_b1 = (const float*)d_in[6];
    const float* l_w2 = (const float*)d_in[7];
    const float* l_b2 = (const float*)d_in[8];
    const float* b_w1 = (const float*)d_in[9];
    const float* b_b1 = (const float*)d_in[10];
    const float* b_w2 = (const float*)d_in[11];
    const float* b_b2 = (const float*)d_in[12];
    const float* gru_k  = (const float*)d_in[13];
    const float* gru_rk = (const float*)d_in[14];
    const float* gru_b  = (const float*)d_in[15];
    const float* i_w1 = (const float*)d_in[16];
    const float* i_b1 = (const float*)d_in[17];
    const float* i_w2 = (const float*)d_in[18];
    const float* i_b2 = (const float*)d_in[19];
    const float* j_w1 = (const float*)d_in[20];
    const float* j_b1 = (const float*)d_in[21];
    const float* j_w2 = (const float*)d_in[22];
    const float* j_b2 = (const float*)d_in[23];
    const float* f_w1 = (const float*)d_in[24];
    const float* f_b1 = (const float*)d_in[25];
    const float* f_w2 = (const float*)d_in[26];
    const float* f_b2 = (const float*)d_in[27];
    float* out = (float*)d_out;

    k_hist_init <<<2500, 256>>>(x, e);
    k_scan_table<<<NT/16 + 1, 256>>>(l_w1, l_b1, l_w2, l_b2, b_w1, b_b1, b_w2, b_b2);
    k_scatter_e <<<2500, 256>>>(first, second);

    for (int p = 0; p < 8; p++){
        k_msg<<<(NT*32)/256, 256>>>();
        k_gru<<<(2*N_NODES + 127)/128, 128>>>(gru_k, gru_rk, gru_b);
    }

    k_readout<<<N_NODES/16, 256>>>(x, segment,
                                   i_w1, i_b1, i_w2, i_b2,
                                   j_w1, j_b1, j_w2, j_b2);
    k_final  <<<N_GRAPHS, 256>>>(f_w1, f_b1, f_w2, f_b2, out);
}

// round 12
// speedup vs baseline: 1.2983x; 1.2983x over previous
#include <cuda_runtime.h>
#include <cstdint>
#include <cstddef>

#define N_NODES 40000
#define N_EDGES 640000
#define N_GRAPHS 64
#define NHH 16
#define NT 16384
#define NWARPS 16384
#define EPW 39                      /* edges per warp; first 1024 warps take 40 */
#define TMIN_T (-8.0f)
#define DT_T (16.0f/(float)(NT-1))
#define INVDT_T ((float)(NT-1)/16.0f)

// ---------------- scratch (device globals; no allocations) ----------------
__device__ __align__(256) float  g_TA [(size_t)NT*256];   // edge matrix table [NT][16][16]
__device__ __align__(256) float  g_TB [(size_t)NT*16];    // edge bias table   [NT][16]
__device__ __align__(256) float  g_h [N_NODES*NHH];
__device__ __align__(256) float  g_m [N_NODES*NHH];
__device__ __align__(256) float  g_nb[N_GRAPHS*256];
__device__ __align__(256) int    g_bin_cnt[NT];           // zero at load; re-zeroed by scan each run
__device__ __align__(256) int    g_bin_cur[NT];           // scatter cursor (reset by scan)
__device__ __align__(256) float2 g_bw[N_EDGES];           // cached (w, i0-as-float-bits)
__device__ __align__(256) float4 g_epk[N_EDGES];          // sorted packed edges

__device__ __forceinline__ float selu_f(float x){
    return x > 0.f ? 1.0507009873554805f * x
                   : 1.7580993408473766f * (expf(x) - 1.f);
}
__device__ __forceinline__ float sigmoid_f(float x){
    return 1.f / (1.f + expf(-x));
}
__device__ __forceinline__ void edge_bin(float t, int& i0, float& w){
    float u = (t - TMIN_T) * INVDT_T;
    u = fminf(fmaxf(u, 0.f), (float)(NT - 1));
    int i = (int)u;
    if (i > NT - 2) i = NT - 2;
    i0 = i;
    w  = u - (float)i;
}

// ---------------- launch 0: state init + edge binning + histogram ----------------
__global__ void k_hist_init(const float* __restrict__ x, const float* __restrict__ e){
    int i = blockIdx.x * blockDim.x + threadIdx.x;   // 0..640000
    if (i < N_GRAPHS*256) g_nb[i] = 0.f;
    if (i < N_NODES*NHH){
        g_m[i] = 0.f;
        int n = i >> 4, j = i & 15;
        g_h[i] = (j < 2) ? x[n*2 + j] : 0.f;
    }
    if (i < N_EDGES){
        int i0; float w;
        edge_bin(e[i], i0, w);
        float2 bw; bw.x = w; bw.y = __int_as_float(i0);
        g_bw[i] = bw;
        atomicAdd(&g_bin_cnt[i0], 1);
    }
}

// ---------------- launch 1: table build (blocks 0..1023) + scan (block 1024) ----------------
__global__ void k_scan_table(const float* __restrict__ lw1, const float* __restrict__ lb1,
                             const float* __restrict__ lw2, const float* __restrict__ lb2,
                             const float* __restrict__ bw1, const float* __restrict__ bb1,
                             const float* __restrict__ bw2, const float* __restrict__ bb2){
    const int TP = 16;
    int tid = threadIdx.x;           // 256

    if (blockIdx.x == NT/TP){
        // ---- exclusive scan over NT bins; write scatter cursor; re-zero cnt ----
        __shared__ int part[256];
        __shared__ int pref[257];
        int base = tid * (NT/256);
        int s = 0;
        #pragma unroll 4
        for (int i = 0; i < NT/256; i++) s += g_bin_cnt[base + i];
        part[tid] = s;
        __syncthreads();
        if (tid == 0){
            int acc = 0;
            pref[0] = 0;
            for (int i = 0; i < 256; i++){ acc += part[i]; pref[i+1] = acc; }
        }
        __syncthreads();
        int off = pref[tid];
        #pragma unroll 4
        for (int i = 0; i < NT/256; i++){
            int c = g_bin_cnt[base + i];
            g_bin_cur[base + i] = off;
            g_bin_cnt[base + i] = 0;          // restore invariant for next replay
            off += c;
        }
        return;
    }

    // ---- table build ----
    __shared__ float s_sh [256][TP];
    __shared__ float sb_sh[256][TP];
    int p0 = blockIdx.x * TP;

    float w1  = lw1[tid], b1  = lb1[tid];
    float w1b = bw1[tid], b1b = bb1[tid];
    #pragma unroll
    for (int p = 0; p < TP; p++){
        float t = TMIN_T + (float)(p0 + p) * DT_T;
        s_sh [tid][p] = selu_f(fmaf(t, w1,  b1));
        sb_sh[tid][p] = selu_f(fmaf(t, w1b, b1b));
    }
    __syncthreads();

    float acc[TP];
    float bias = lb2[tid];
    #pragma unroll
    for (int p = 0; p < TP; p++) acc[p] = bias;
    for (int k = 0; k < 256; k++){
        float w = lw2[k*256 + tid];
        const float4* s4 = (const float4*)&s_sh[k][0];
        #pragma unroll
        for (int q = 0; q < TP/4; q++){
            float4 s = s4[q];
            acc[q*4+0] = fmaf(s.x, w, acc[q*4+0]);
            acc[q*4+1] = fmaf(s.y, w, acc[q*4+1]);
            acc[q*4+2] = fmaf(s.z, w, acc[q*4+2]);
            acc[q*4+3] = fmaf(s.w, w, acc[q*4+3]);
        }
    }
    #pragma unroll
    for (int p = 0; p < TP; p++)
        g_TA[(size_t)(p0 + p)*256 + tid] = acc[p];

    int o = tid & 15, p = tid >> 4;
    float acc2 = bb2[o];
    for (int k = 0; k < 256; k++)
        acc2 = fmaf(sb_sh[k][p], bw2[k*16 + o], acc2);
    g_TB[(size_t)(p0 + p)*16 + o] = acc2;
}

// ---------------- launch 2: scatter edges into bin-sorted packed array ----------------
__global__ void k_scatter_e(const int* __restrict__ first, const int* __restrict__ second){
    int idx = blockIdx.x * blockDim.x + threadIdx.x;
    if (idx >= N_EDGES) return;
    float2 bw = g_bw[idx];
    int i0 = __float_as_int(bw.y);
    int pos = atomicAdd(&g_bin_cur[i0], 1);
    float4 pk;
    pk.x = bw.x;
    pk.y = bw.y;
    pk.z = __int_as_float(first[idx]);
    pk.w = __int_as_float(second[idx]);
    g_epk[pos] = pk;
}

// ---------------- message pass: warp per edge-range, cached-bin A registers ----------------
// lane = (row = l&15, khalf = l>>4). A half-rows of the current bin pair live in
// registers; reloaded only on (warp-uniform) bin change. 4 edges batched per
// iteration for MLP. Per edge: 1 uniform epk wf, 2 h wf, 16 FMA, 2 shfl, 1 red wf.
__global__ void __launch_bounds__(256)
k_msg(){
    int gw   = (blockIdx.x * blockDim.x + threadIdx.x) >> 5;
    int lane = threadIdx.x & 31;
    if (gw >= NWARPS) return;
    int row = lane & 15, khalf = lane >> 4;

    int start = gw * EPW + min(gw, 1024);
    int end   = start + EPW + (gw < 1024 ? 1 : 0);

    int   curbin = -1;
    float4 a00, a01, a10, a11;
    float b0r = 0.f, b1r = 0.f;

    for (int base = start; base < end; base += 4){
        int n = end - base; if (n > 4) n = 4;

        float4 pk[4];
        #pragma unroll
        for (int k = 0; k < 4; k++){
            int e = base + k; if (e >= end) e = end - 1;
            pk[k] = g_epk[e];                     // warp-uniform address
        }
        float4 h0[4], h1[4];
        #pragma unroll
        for (int k = 0; k < 4; k++){
            int f = __float_as_int(pk[k].z);
            const float4* hp = (const float4*)(g_h + f * NHH + khalf * 8);
            h0[k] = hp[0]; h1[k] = hp[1];
        }

        #pragma unroll
        for (int k = 0; k < 4; k++){
            if (k >= n) break;
            int i0 = __float_as_int(pk[k].y);     // warp-uniform
            if (i0 != curbin){                    // warp-uniform branch (rare)
                const float4* a0p = (const float4*)(g_TA + (size_t)i0*256 + row*16 + khalf*8);
                a00 = a0p[0]; a01 = a0p[1];
                a10 = a0p[64]; a11 = a0p[65];     // +256 floats = next bin row
                b0r = g_TB[(size_t)i0*16 + row];
                b1r = g_TB[(size_t)(i0+1)*16 + row];
                curbin = i0;
            }
            float w = pk[k].x, w0 = 1.f - w;
            int   s = __float_as_int(pk[k].w);

            float p0 = 0.f, p1 = 0.f;
            p0 = fmaf(a00.x, h0[k].x, p0); p0 = fmaf(a00.y, h0[k].y, p0);
            p0 = fmaf(a00.z, h0[k].z, p0); p0 = fmaf(a00.w, h0[k].w, p0);
            p0 = fmaf(a01.x, h1[k].x, p0); p0 = fmaf(a01.y, h1[k].y, p0);
            p0 = fmaf(a01.z, h1[k].z, p0); p0 = fmaf(a01.w, h1[k].w, p0);
            p1 = fmaf(a10.x, h0[k].x, p1); p1 = fmaf(a10.y, h0[k].y, p1);
            p1 = fmaf(a10.z, h0[k].z, p1); p1 = fmaf(a10.w, h0[k].w, p1);
            p1 = fmaf(a11.x, h1[k].x, p1); p1 = fmaf(a11.y, h1[k].y, p1);
            p1 = fmaf(a11.z, h1[k].z, p1); p1 = fmaf(a11.w, h1[k].w, p1);

            float q0 = __shfl_down_sync(0xffffffffu, p0, 16);
            float q1 = __shfl_down_sync(0xffffffffu, p1, 16);
            float m  = fmaf(w0, p0 + q0 + b0r, w * (p1 + q1 + b1r));
            if (lane < 16){
                asm volatile("red.global.add.f32 [%0], %1;"
                             :: "l"(g_m + (size_t)s * NHH + row), "f"(m) : "memory");
            }
        }
    }
}

// ---------------- GRU update: 2 threads per node ----------------
__global__ void k_gru(const float* __restrict__ gk, const float* __restrict__ grk,
                      const float* __restrict__ gb){
    __shared__ float K[16*48], RK[16*48], B[96];
    int tid = threadIdx.x;  // 128
    for (int i = tid; i < 768; i += blockDim.x){ K[i] = gk[i]; RK[i] = grk[i]; }
    if (tid < 96) B[tid] = gb[tid];
    __syncthreads();

    int idx = blockIdx.x * blockDim.x + tid;
    if (idx >= 2*N_NODES) return;
    int n = idx >> 1, half = idx & 1;

    float m[16], h[16];
    float4* mp = (float4*)(g_m + n * NHH);
    float4* hp = (float4*)(g_h + n * NHH);
    #pragma unroll
    for (int q = 0; q < 4; q++){
        float4 a = mp[q]; m[q*4+0]=a.x; m[q*4+1]=a.y; m[q*4+2]=a.z; m[q*4+3]=a.w;
        float4 b = hp[q]; h[q*4+0]=b.x; h[q*4+1]=b.y; h[q*4+2]=b.z; h[q*4+3]=b.w;
    }

    float hn[8];
    int base = half * 8;
    #pragma unroll
    for (int ii = 0; ii < 8; ii++){
        int i = base + ii;
        float xz = B[i], xr = B[16+i], xh = B[32+i];
        float rz = B[48+i], rr = B[64+i], rh = B[80+i];
        #pragma unroll
        for (int j = 0; j < 16; j++){
            float mj = m[j], hj = h[j];
            xz = fmaf(mj, K [j*48 + i],      xz);
            xr = fmaf(mj, K [j*48 + 16 + i], xr);
            xh = fmaf(mj, K [j*48 + 32 + i], xh);
            rz = fmaf(hj, RK[j*48 + i],      rz);
            rr = fmaf(hj, RK[j*48 + 16 + i], rr);
            rh = fmaf(hj, RK[j*48 + 32 + i], rh);
        }
        float z  = sigmoid_f(xz + rz);
        float r  = sigmoid_f(xr + rr);
        float hh = tanhf(fmaf(r, rh, xh));
        hn[ii] = z * h[i] + (1.f - z) * hh;
    }
    float4 zero = {0.f, 0.f, 0.f, 0.f};
    #pragma unroll
    for (int q = 0; q < 2; q++){
        float4 o;
        o.x = hn[q*4+0]; o.y = hn[q*4+1]; o.z = hn[q*4+2]; o.w = hn[q*4+3];
        hp[half*2 + q] = o;
        mp[half*2 + q] = zero;
    }
}

// ---------------- fused readout ----------------
__global__ void __launch_bounds__(256)
k_readout(const float* __restrict__ x, const int* __restrict__ seg,
          const float* __restrict__ iw1, const float* __restrict__ ib1,
          const float* __restrict__ iw2, const float* __restrict__ ib2,
          const float* __restrict__ jw1, const float* __restrict__ jb1,
          const float* __restrict__ jw2, const float* __restrict__ jb2){
    const int NPB = 16;
    __shared__ float2 tu[NPB][256];
    __shared__ float  hx[NPB][18];
    __shared__ int    segs[NPB];
    int n0  = blockIdx.x * NPB;
    int tid = threadIdx.x;   // 256

    for (int i = tid; i < NPB*18; i += 256){
        int p = i / 18, d = i % 18;
        int n = n0 + p;
        hx[p][d] = (d < 16) ? g_h[n*16 + d] : x[n*2 + (d - 16)];
    }
    if (tid < NPB) segs[tid] = seg[n0 + tid];
    __syncthreads();

    {
        float ai[NPB], aj[NPB];
        float bi = ib1[tid], bj = jb1[tid];
        #pragma unroll
        for (int p = 0; p < NPB; p++){ ai[p] = bi; aj[p] = bj; }
        #pragma unroll
        for (int d = 0; d < 18; d++){
            float wi = iw1[d*256 + tid], wj = jw1[d*256 + tid];
            #pragma unroll
            for (int p = 0; p < NPB; p++){
                float hv = hx[p][d];
                ai[p] = fmaf(hv, wi, ai[p]);
                aj[p] = fmaf(hv, wj, aj[p]);
            }
        }
        #pragma unroll
        for (int p = 0; p < NPB; p++){
            float2 v; v.x = tanhf(ai[p]); v.y = selu_f(aj[p]);
            tu[p][tid] = v;
        }
    }
    __syncthreads();

    float g1[NPB], g2[NPB];
    {
        float b2i = ib2[tid], b2j = jb2[tid];
        #pragma unroll
        for (int p = 0; p < NPB; p++){ g1[p] = b2i; g2[p] = b2j; }
        for (int k = 0; k < 256; k++){
            float wi = iw2[(size_t)k*256 + tid];
            float wj = jw2[(size_t)k*256 + tid];
            #pragma unroll
            for (int p = 0; p < NPB; p++){
                float2 v = tu[p][k];
                g1[p] = fmaf(v.x, wi, g1[p]);
                g2[p] = fmaf(v.y, wj, g2[p]);
            }
        }
    }

    int cur = segs[0];
    float acc = 0.f;
    #pragma unroll
    for (int p = 0; p < NPB; p++){
        int s = segs[p];
        if (s != cur){
            atomicAdd(&g_nb[cur*256 + tid], acc);
            acc = 0.f; cur = s;
        }
        acc = fmaf(sigmoid_f(g1[p]), g2[p], acc);
    }
    atomicAdd(&g_nb[cur*256 + tid], acc);
}

// ---------------- final MLP ----------------
__global__ void k_final(const float* __restrict__ fw1, const float* __restrict__ fb1,
                        const float* __restrict__ fw2, const float* __restrict__ fb2,
                        float* __restrict__ out){
    __shared__ float nb_sh[256];
    __shared__ float red[256];
    int g = blockIdx.x, o = threadIdx.x;
    nb_sh[o] = g_nb[g*256 + o];
    __syncthreads();
    float acc = fb1[o];
    for (int k = 0; k < 256; k++)
        acc = fmaf(nb_sh[k], fw1[k*256 + o], acc);
    red[o] = selu_f(acc) * fw2[o];
    __syncthreads();
    for (int s = 128; s > 0; s >>= 1){
        if (o < s) red[o] += red[o + s];
        __syncthreads();
    }
    if (o == 0) out[g] = red[0] + fb2[0];
}

// ---------------- launch ----------------
extern "C" void kernel_launch(void* const* d_in, const int* in_sizes, int n_in,
                              void* d_out, int out_size){
    const float* x       = (const float*)d_in[0];
    const float* e       = (const float*)d_in[1];
    const int*   first   = (const int*)  d_in[2];
    const int*   second  = (const int*)  d_in[3];
    const int*   segment = (const int*)  d_in[4];
    const float* l_w1 = (const float*)d_in[5];
    const float* l_b1 = (const float*)d_in[6];
    const float* l_w2 = (const float*)d_in[7];
    const float* l_b2 = (const float*)d_in[8];
    const float* b_w1 = (const float*)d_in[9];
    const float* b_b1 = (const float*)d_in[10];
    const float* b_w2 = (const float*)d_in[11];
    const float* b_b2 = (const float*)d_in[12];
    const float* gru_k  = (const float*)d_in[13];
    const float* gru_rk = (const float*)d_in[14];
    const float* gru_b  = (const float*)d_in[15];
    const float* i_w1 = (const float*)d_in[16];
    const float* i_b1 = (const float*)d_in[17];
    const float* i_w2 = (const float*)d_in[18];
    const float* i_b2 = (const float*)d_in[19];
    const float* j_w1 = (const float*)d_in[20];
    const float* j_b1 = (const float*)d_in[21];
    const float* j_w2 = (const float*)d_in[22];
    const float* j_b2 = (const float*)d_in[23];
    const float* f_w1 = (const float*)d_in[24];
    const float* f_b1 = (const float*)d_in[25];
    const float* f_w2 = (const float*)d_in[26];
    const float* f_b2 = (const float*)d_in[27];
    float* out = (float*)d_out;

    k_hist_init <<<2500, 256>>>(x, e);
    k_scan_table<<<NT/16 + 1, 256>>>(l_w1, l_b1, l_w2, l_b2, b_w1, b_b1, b_w2, b_b2);
    k_scatter_e <<<2500, 256>>>(first, second);

    for (int p = 0; p < 8; p++){
        k_msg<<<(NWARPS*32)/256, 256>>>();
        k_gru<<<(2*N_NODES + 127)/128, 128>>>(gru_k, gru_rk, gru_b);
    }

    k_readout<<<N_NODES/16, 256>>>(x, segment,
                                   i_w1, i_b1, i_w2, i_b2,
                                   j_w1, j_b1, j_w2, j_b2);
    k_final  <<<N_GRAPHS, 256>>>(f_w1, f_b1, f_w2, f_b2, out);
}

// round 14
// speedup vs baseline: 1.4014x; 1.0794x over previous
#include <cuda_runtime.h>
#include <cstdint>
#include <cstddef>

#define N_NODES 40000
#define N_EDGES 640000
#define N_GRAPHS 64
#define NHH 16
#define NT 16384
#define EPW 40
#define NWARPS_MSG (N_EDGES/EPW)    /* 16000 exactly */
#define TMIN_T (-8.0f)
#define DT_T (16.0f/(float)(NT-1))
#define INVDT_T ((float)(NT-1)/16.0f)

// ---------------- scratch (device globals; no allocations) ----------------
__device__ __align__(256) float  g_TA [(size_t)NT*256];   // edge matrix table [NT][16][16]
__device__ __align__(256) float  g_TB [(size_t)NT*16];    // edge bias table   [NT][16]
__device__ __align__(256) float  g_h [N_NODES*NHH];
__device__ __align__(256) float  g_m [N_NODES*NHH];
__device__ __align__(256) float  g_nb[N_GRAPHS*256];
__device__ __align__(256) int    g_bin_cnt[NT];           // zero at load; re-zeroed by scan each run
__device__ __align__(256) int    g_bin_cur[NT];           // scatter cursor (reset by scan)
__device__ __align__(256) float2 g_bw[N_EDGES];           // cached (w, i0-as-float-bits)
__device__ __align__(256) float4 g_epk[N_EDGES];          // sorted packed edges (w, i0, f*16, s*16)

__device__ __forceinline__ float selu_f(float x){
    return x > 0.f ? 1.0507009873554805f * x
                   : 1.7580993408473766f * (expf(x) - 1.f);
}
__device__ __forceinline__ float sigmoid_f(float x){
    return 1.f / (1.f + expf(-x));
}
__device__ __forceinline__ void edge_bin(float t, int& i0, float& w){
    float u = (t - TMIN_T) * INVDT_T;
    u = fminf(fmaxf(u, 0.f), (float)(NT - 1));
    int i = (int)u;
    if (i > NT - 2) i = NT - 2;
    i0 = i;
    w  = u - (float)i;
}

// ---------------- launch 0: state init + edge binning + histogram ----------------
__global__ void k_hist_init(const float* __restrict__ x, const float* __restrict__ e){
    int i = blockIdx.x * blockDim.x + threadIdx.x;   // 0..640000
    if (i < N_GRAPHS*256) g_nb[i] = 0.f;
    if (i < N_NODES*NHH){
        g_m[i] = 0.f;
        int n = i >> 4, j = i & 15;
        g_h[i] = (j < 2) ? x[n*2 + j] : 0.f;
    }
    if (i < N_EDGES){
        int i0; float w;
        edge_bin(e[i], i0, w);
        float2 bw; bw.x = w; bw.y = __int_as_float(i0);
        g_bw[i] = bw;
        atomicAdd(&g_bin_cnt[i0], 1);
    }
}

// ---------------- launch 1: table build (blocks 0..1023) + scan (block 1024) ----------------
__global__ void k_scan_table(const float* __restrict__ lw1, const float* __restrict__ lb1,
                             const float* __restrict__ lw2, const float* __restrict__ lb2,
                             const float* __restrict__ bw1, const float* __restrict__ bb1,
                             const float* __restrict__ bw2, const float* __restrict__ bb2){
    const int TP = 16;
    int tid = threadIdx.x;           // 256

    if (blockIdx.x == NT/TP){
        // ---- exclusive scan over NT bins; write scatter cursor; re-zero cnt ----
        __shared__ int part[256];
        __shared__ int pref[257];
        int base = tid * (NT/256);
        int s = 0;
        #pragma unroll 4
        for (int i = 0; i < NT/256; i++) s += g_bin_cnt[base + i];
        part[tid] = s;
        __syncthreads();
        if (tid == 0){
            int acc = 0;
            pref[0] = 0;
            for (int i = 0; i < 256; i++){ acc += part[i]; pref[i+1] = acc; }
        }
        __syncthreads();
        int off = pref[tid];
        #pragma unroll 4
        for (int i = 0; i < NT/256; i++){
            int c = g_bin_cnt[base + i];
            g_bin_cur[base + i] = off;
            g_bin_cnt[base + i] = 0;          // restore invariant for next replay
            off += c;
        }
        return;
    }

    // ---- table build ----
    __shared__ float s_sh [256][TP];
    __shared__ float sb_sh[256][TP];
    int p0 = blockIdx.x * TP;

    float w1  = lw1[tid], b1  = lb1[tid];
    float w1b = bw1[tid], b1b = bb1[tid];
    #pragma unroll
    for (int p = 0; p < TP; p++){
        float t = TMIN_T + (float)(p0 + p) * DT_T;
        s_sh [tid][p] = selu_f(fmaf(t, w1,  b1));
        sb_sh[tid][p] = selu_f(fmaf(t, w1b, b1b));
    }
    __syncthreads();

    float acc[TP];
    float bias = lb2[tid];
    #pragma unroll
    for (int p = 0; p < TP; p++) acc[p] = bias;
    for (int k = 0; k < 256; k++){
        float w = lw2[k*256 + tid];
        const float4* s4 = (const float4*)&s_sh[k][0];
        #pragma unroll
        for (int q = 0; q < TP/4; q++){
            float4 s = s4[q];
            acc[q*4+0] = fmaf(s.x, w, acc[q*4+0]);
            acc[q*4+1] = fmaf(s.y, w, acc[q*4+1]);
            acc[q*4+2] = fmaf(s.z, w, acc[q*4+2]);
            acc[q*4+3] = fmaf(s.w, w, acc[q*4+3]);
        }
    }
    #pragma unroll
    for (int p = 0; p < TP; p++)
        g_TA[(size_t)(p0 + p)*256 + tid] = acc[p];

    int o = tid & 15, p = tid >> 4;
    float acc2 = bb2[o];
    for (int k = 0; k < 256; k++)
        acc2 = fmaf(sb_sh[k][p], bw2[k*16 + o], acc2);
    g_TB[(size_t)(p0 + p)*16 + o] = acc2;
}

// ---------------- launch 2: scatter edges (pre-multiplied node offsets) ----------------
__global__ void k_scatter_e(const int* __restrict__ first, const int* __restrict__ second){
    int idx = blockIdx.x * blockDim.x + threadIdx.x;
    if (idx >= N_EDGES) return;
    float2 bw = g_bw[idx];
    int i0 = __float_as_int(bw.y);
    int pos = atomicAdd(&g_bin_cur[i0], 1);
    float4 pk;
    pk.x = bw.x;
    pk.y = bw.y;
    pk.z = __int_as_float(first[idx]  * NHH);
    pk.w = __int_as_float(second[idx] * NHH);
    g_epk[pos] = pk;
}

// ---------------- message pass: warp per 40 edges, cached-bin A regs, dual-red ----------------
// lane = (row = l&15, khalf = l>>4). A half-rows of current bin pair in registers,
// reloaded on (warp-uniform) bin change. 2 edges per iteration; shfl_xor(16) gives
// the full dot on ALL lanes, so one red instruction commits both edges (lanes 0-15
// edge0, lanes 16-31 edge1).
__global__ void __launch_bounds__(256, 4)
k_msg(){
    int gw   = (blockIdx.x * blockDim.x + threadIdx.x) >> 5;   // 0..15999
    int lane = threadIdx.x & 31;
    int row = lane & 15, khalf = lane >> 4;
    int base = gw * EPW;

    int    curbin = -1;
    float4 a00, a01, a10, a11;
    float  b0r = 0.f, b1r = 0.f;

    #pragma unroll 1
    for (int it = 0; it < EPW/2; it++){
        int e0 = base + 2*it;
        float4 pk0 = g_epk[e0];                 // warp-uniform
        float4 pk1 = g_epk[e0 + 1];
        int f0 = __float_as_int(pk0.z);
        int f1 = __float_as_int(pk1.z);
        const float4* hp0 = (const float4*)(g_h + f0 + khalf*8);
        const float4* hp1 = (const float4*)(g_h + f1 + khalf*8);
        float4 h00 = hp0[0], h01 = hp0[1];
        float4 h10 = hp1[0], h11 = hp1[1];

        float mm0, mm1;
        #pragma unroll
        for (int k = 0; k < 2; k++){
            float4 pk  = k ? pk1 : pk0;
            float4 hx0 = k ? h10 : h00;
            float4 hx1 = k ? h11 : h01;
            int i0 = __float_as_int(pk.y);      // warp-uniform
            if (i0 != curbin){                  // warp-uniform branch (rare)
                const float4* a0p = (const float4*)(g_TA + (size_t)i0*256 + row*16 + khalf*8);
                a00 = a0p[0];  a01 = a0p[1];
                a10 = a0p[64]; a11 = a0p[65];   // +256 floats = next table row
                b0r = g_TB[(size_t)i0*16 + row];
                b1r = g_TB[(size_t)(i0+1)*16 + row];
                curbin = i0;
            }
            float w = pk.x;
            float p0 = 0.f, p1 = 0.f;
            p0 = fmaf(a00.x, hx0.x, p0); p0 = fmaf(a00.y, hx0.y, p0);
            p0 = fmaf(a00.z, hx0.z, p0); p0 = fmaf(a00.w, hx0.w, p0);
            p0 = fmaf(a01.x, hx1.x, p0); p0 = fmaf(a01.y, hx1.y, p0);
            p0 = fmaf(a01.z, hx1.z, p0); p0 = fmaf(a01.w, hx1.w, p0);
            p1 = fmaf(a10.x, hx0.x, p1); p1 = fmaf(a10.y, hx0.y, p1);
            p1 = fmaf(a10.z, hx0.z, p1); p1 = fmaf(a10.w, hx0.w, p1);
            p1 = fmaf(a11.x, hx1.x, p1); p1 = fmaf(a11.y, hx1.y, p1);
            p1 = fmaf(a11.z, hx1.z, p1); p1 = fmaf(a11.w, hx1.w, p1);

            float q0 = __shfl_xor_sync(0xffffffffu, p0, 16);
            float q1 = __shfl_xor_sync(0xffffffffu, p1, 16);
            float m  = fmaf(1.f - w, p0 + q0 + b0r, w * (p1 + q1 + b1r));
            if (k) mm1 = m; else mm0 = m;
        }
        int s0 = __float_as_int(pk0.w);
        int s1 = __float_as_int(pk1.w);
        float mv = (lane < 16) ? mm0 : mm1;
        int   sv = (lane < 16) ? s0  : s1;
        asm volatile("red.global.add.f32 [%0], %1;"
                     :: "l"(g_m + sv + row), "f"(mv) : "memory");
    }
}

// ---------------- GRU update: 2 threads per node ----------------
__global__ void k_gru(const float* __restrict__ gk, const float* __restrict__ grk,
                      const float* __restrict__ gb){
    __shared__ float K[16*48], RK[16*48], B[96];
    int tid = threadIdx.x;  // 128
    for (int i = tid; i < 768; i += blockDim.x){ K[i] = gk[i]; RK[i] = grk[i]; }
    if (tid < 96) B[tid] = gb[tid];
    __syncthreads();

    int idx = blockIdx.x * blockDim.x + tid;
    if (idx >= 2*N_NODES) return;
    int n = idx >> 1, half = idx & 1;

    float m[16], h[16];
    float4* mp = (float4*)(g_m + n * NHH);
    float4* hp = (float4*)(g_h + n * NHH);
    #pragma unroll
    for (int q = 0; q < 4; q++){
        float4 a = mp[q]; m[q*4+0]=a.x; m[q*4+1]=a.y; m[q*4+2]=a.z; m[q*4+3]=a.w;
        float4 b = hp[q]; h[q*4+0]=b.x; h[q*4+1]=b.y; h[q*4+2]=b.z; h[q*4+3]=b.w;
    }

    float hn[8];
    int base = half * 8;
    #pragma unroll
    for (int ii = 0; ii < 8; ii++){
        int i = base + ii;
        float xz = B[i], xr = B[16+i], xh = B[32+i];
        float rz = B[48+i], rr = B[64+i], rh = B[80+i];
        #pragma unroll
        for (int j = 0; j < 16; j++){
            float mj = m[j], hj = h[j];
            xz = fmaf(mj, K [j*48 + i],      xz);
            xr = fmaf(mj, K [j*48 + 16 + i], xr);
            xh = fmaf(mj, K [j*48 + 32 + i], xh);
            rz = fmaf(hj, RK[j*48 + i],      rz);
            rr = fmaf(hj, RK[j*48 + 16 + i], rr);
            rh = fmaf(hj, RK[j*48 + 32 + i], rh);
        }
        float z  = sigmoid_f(xz + rz);
        float r  = sigmoid_f(xr + rr);
        float hh = tanhf(fmaf(r, rh, xh));
        hn[ii] = z * h[i] + (1.f - z) * hh;
    }
    float4 zero = {0.f, 0.f, 0.f, 0.f};
    #pragma unroll
    for (int q = 0; q < 2; q++){
        float4 o;
        o.x = hn[q*4+0]; o.y = hn[q*4+1]; o.z = hn[q*4+2]; o.w = hn[q*4+3];
        hp[half*2 + q] = o;
        mp[half*2 + q] = zero;
    }
}

// ---------------- fused readout ----------------
__global__ void __launch_bounds__(256)
k_readout(const float* __restrict__ x, const int* __restrict__ seg,
          const float* __restrict__ iw1, const float* __restrict__ ib1,
          const float* __restrict__ iw2, const float* __restrict__ ib2,
          const float* __restrict__ jw1, const float* __restrict__ jb1,
          const float* __restrict__ jw2, const float* __restrict__ jb2){
    const int NPB = 16;
    __shared__ float2 tu[NPB][256];
    __shared__ float  hx[NPB][18];
    __shared__ int    segs[NPB];
    int n0  = blockIdx.x * NPB;
    int tid = threadIdx.x;   // 256

    for (int i = tid; i < NPB*18; i += 256){
        int p = i / 18, d = i % 18;
        int n = n0 + p;
        hx[p][d] = (d < 16) ? g_h[n*16 + d] : x[n*2 + (d - 16)];
    }
    if (tid < NPB) segs[tid] = seg[n0 + tid];
    __syncthreads();

    {
        float ai[NPB], aj[NPB];
        float bi = ib1[tid], bj = jb1[tid];
        #pragma unroll
        for (int p = 0; p < NPB; p++){ ai[p] = bi; aj[p] = bj; }
        #pragma unroll
        for (int d = 0; d < 18; d++){
            float wi = iw1[d*256 + tid], wj = jw1[d*256 + tid];
            #pragma unroll
            for (int p = 0; p < NPB; p++){
                float hv = hx[p][d];
                ai[p] = fmaf(hv, wi, ai[p]);
                aj[p] = fmaf(hv, wj, aj[p]);
            }
        }
        #pragma unroll
        for (int p = 0; p < NPB; p++){
            float2 v; v.x = tanhf(ai[p]); v.y = selu_f(aj[p]);
            tu[p][tid] = v;
        }
    }
    __syncthreads();

    float g1[NPB], g2[NPB];
    {
        float b2i = ib2[tid], b2j = jb2[tid];
        #pragma unroll
        for (int p = 0; p < NPB; p++){ g1[p] = b2i; g2[p] = b2j; }
        for (int k = 0; k < 256; k++){
            float wi = iw2[(size_t)k*256 + tid];
            float wj = jw2[(size_t)k*256 + tid];
            #pragma unroll
            for (int p = 0; p < NPB; p++){
                float2 v = tu[p][k];
                g1[p] = fmaf(v.x, wi, g1[p]);
                g2[p] = fmaf(v.y, wj, g2[p]);
            }
        }
    }

    int cur = segs[0];
    float acc = 0.f;
    #pragma unroll
    for (int p = 0; p < NPB; p++){
        int s = segs[p];
        if (s != cur){
            atomicAdd(&g_nb[cur*256 + tid], acc);
            acc = 0.f; cur = s;
        }
        acc = fmaf(sigmoid_f(g1[p]), g2[p], acc);
    }
    atomicAdd(&g_nb[cur*256 + tid], acc);
}

// ---------------- final MLP ----------------
__global__ void k_final(const float* __restrict__ fw1, const float* __restrict__ fb1,
                        const float* __restrict__ fw2, const float* __restrict__ fb2,
                        float* __restrict__ out){
    __shared__ float nb_sh[256];
    __shared__ float red[256];
    int g = blockIdx.x, o = threadIdx.x;
    nb_sh[o] = g_nb[g*256 + o];
    __syncthreads();
    float acc = fb1[o];
    for (int k = 0; k < 256; k++)
        acc = fmaf(nb_sh[k], fw1[k*256 + o], acc);
    red[o] = selu_f(acc) * fw2[o];
    __syncthreads();
    for (int s = 128; s > 0; s >>= 1){
        if (o < s) red[o] += red[o + s];
        __syncthreads();
    }
    if (o == 0) out[g] = red[0] + fb2[0];
}

// ---------------- launch ----------------
extern "C" void kernel_launch(void* const* d_in, const int* in_sizes, int n_in,
                              void* d_out, int out_size){
    const float* x       = (const float*)d_in[0];
    const float* e       = (const float*)d_in[1];
    const int*   first   = (const int*)  d_in[2];
    const int*   second  = (const int*)  d_in[3];
    const int*   segment = (const int*)  d_in[4];
    const float* l_w1 = (const float*)d_in[5];
    const float* l_b1 = (const float*)d_in[6];
    const float* l_w2 = (const float*)d_in[7];
    const float* l_b2 = (const float*)d_in[8];
    const float* b_w1 = (const float*)d_in[9];
    const float* b_b1 = (const float*)d_in[10];
    const float* b_w2 = (const float*)d_in[11];
    const float* b_b2 = (const float*)d_in[12];
    const float* gru_k  = (const float*)d_in[13];
    const float* gru_rk = (const float*)d_in[14];
    const float* gru_b  = (const float*)d_in[15];
    const float* i_w1 = (const float*)d_in[16];
    const float* i_b1 = (const float*)d_in[17];
    const float* i_w2 = (const float*)d_in[18];
    const float* i_b2 = (const float*)d_in[19];
    const float* j_w1 = (const float*)d_in[20];
    const float* j_b1 = (const float*)d_in[21];
    const float* j_w2 = (const float*)d_in[22];
    const float* j_b2 = (const float*)d_in[23];
    const float* f_w1 = (const float*)d_in[24];
    const float* f_b1 = (const float*)d_in[25];
    const float* f_w2 = (const float*)d_in[26];
    const float* f_b2 = (const float*)d_in[27];
    float* out = (float*)d_out;

    k_hist_init <<<2500, 256>>>(x, e);
    k_scan_table<<<NT/16 + 1, 256>>>(l_w1, l_b1, l_w2, l_b2, b_w1, b_b1, b_w2, b_b2);
    k_scatter_e <<<2500, 256>>>(first, second);

    for (int p = 0; p < 8; p++){
        k_msg<<<(NWARPS_MSG*32)/256, 256>>>();
        k_gru<<<(2*N_NODES + 127)/128, 128>>>(gru_k, gru_rk, gru_b);
    }

    k_readout<<<N_NODES/16, 256>>>(x, segment,
                                   i_w1, i_b1, i_w2, i_b2,
                                   j_w1, j_b1, j_w2, j_b2);
    k_final  <<<N_GRAPHS, 256>>>(f_w1, f_b1, f_w2, f_b2, out);
}